// round 2
// baseline (speedup 1.0000x reference)
#include <cuda_runtime.h>
#include <math.h>

#define NNODE 50000
#define EMB 35
#define DEG 32
#define NBSTRIDE 40   // padded row: 160B, 32B aligned

typedef unsigned long long ull;

// ---------------- scratch (device globals; no runtime allocation) ----------------
__device__ float g_nb[4][NNODE * NBSTRIDE];  // transformed neighbor embeddings (padded rows)
__device__ float g_sb[4][NNODE];             // per-node dst-side attention score
__device__ float g_sa[4][NNODE];             // per-node src-side attention score
__device__ float g_m [4][NNODE * EMB];       // aggregation results

// ---------------- packed f32x2 helpers ----------------
static __device__ __forceinline__ ull pack2(float a, float b) {
    ull r;
    unsigned int lo = __float_as_uint(a), hi = __float_as_uint(b);
    asm("mov.b64 %0, {%1, %2};" : "=l"(r) : "r"(lo), "r"(hi));
    return r;
}
static __device__ __forceinline__ void unpack2(ull v, float &a, float &b) {
    unsigned int lo, hi;
    asm("mov.b64 {%0, %1}, %2;" : "=r"(lo), "=r"(hi) : "l"(v));
    a = __uint_as_float(lo);
    b = __uint_as_float(hi);
}
#define FMA2(d, a, b, c) \
    asm("fma.rn.f32x2 %0, %1, %2, %3;" : "=l"(d) : "l"(a), "l"(b), "l"(c))
#define ADD2(d, a, b) \
    asm("add.rn.f32x2 %0, %1, %2;" : "=l"(d) : "l"(a), "l"(b))

// ---------------- kernel args ----------------
struct TArgs {
    const float* fsrc[4];
    const float* fdst[4];
    const float* W[4];
    const float* b[4];
    const float* att[4];
};
struct AArgs {
    const int* dst[4];
};

// =====================================================================
// Kernel 1: nb = fsrc @ W + b ; s_b = nb @ att[35:70] ; s_a = fdst @ att[0:35]
// =====================================================================
__global__ __launch_bounds__(128) void transform_kernel(TArgs args) {
    const int jid = blockIdx.y;
    const float* __restrict__ fsrc = args.fsrc[jid];
    const float* __restrict__ fdst = args.fdst[jid];
    const float* __restrict__ W    = args.W[jid];
    const float* __restrict__ bv   = args.b[jid];
    const float* __restrict__ att  = args.att[jid];

    __shared__ __align__(16) float Wsh[EMB * 36];
    __shared__ __align__(16) ull bp[18];
    __shared__ __align__(16) ull ahp[18];
    __shared__ __align__(16) float alo[EMB];

    const int tid = threadIdx.x;
    for (int i = tid; i < EMB * 36; i += blockDim.x) {
        int k = i / 36, c = i % 36;
        Wsh[i] = (c < EMB) ? W[k * EMB + c] : 0.0f;
    }
    if (tid < 18) {
        int c = 2 * tid;
        float b0 = bv[c];
        float b1 = (c + 1 < EMB) ? bv[c + 1] : 0.0f;
        bp[tid] = pack2(b0, b1);
        float a0 = att[EMB + c];
        float a1 = (c + 1 < EMB) ? att[EMB + c + 1] : 0.0f;
        ahp[tid] = pack2(a0, a1);
    }
    if (tid < EMB) alo[tid] = att[tid];
    __syncthreads();

    const int row = blockIdx.x * blockDim.x + tid;
    if (row >= NNODE) return;

    ull acc[18];
#pragma unroll
    for (int i = 0; i < 18; i++) acc[i] = bp[i];

    const float* xr = fsrc + row * EMB;
    for (int k = 0; k < EMB; k++) {
        float xv = __ldg(xr + k);
        ull xx = pack2(xv, xv);
        const ulonglong2* wr = reinterpret_cast<const ulonglong2*>(Wsh + k * 36);
#pragma unroll
        for (int i = 0; i < 9; i++) {
            ulonglong2 wv = wr[i];
            FMA2(acc[2 * i],     wv.x, xx, acc[2 * i]);
            FMA2(acc[2 * i + 1], wv.y, xx, acc[2 * i + 1]);
        }
    }

    ull sp = 0ull;
#pragma unroll
    for (int i = 0; i < 18; i++) FMA2(sp, acc[i], ahp[i], sp);
    float s0, s1;
    unpack2(sp, s0, s1);
    g_sb[jid][row] = s0 + s1;

    ull* outr = reinterpret_cast<ull*>(&g_nb[jid][row * NBSTRIDE]);
#pragma unroll
    for (int i = 0; i < 18; i++) outr[i] = acc[i];

    const float* yr = fdst + row * EMB;
    float sa = 0.0f;
    for (int k = 0; k < EMB; k++) sa = fmaf(__ldg(yr + k), alo[k], sa);
    g_sa[jid][row] = sa;
}

// =====================================================================
// Kernel 2: attention aggregation. One warp per node (DEG==32 lanes).
// =====================================================================
__global__ __launch_bounds__(256) void agg_kernel(AArgs args) {
    const int jid = blockIdx.y;
    const float* __restrict__ nb  = g_nb[jid];
    const float* __restrict__ sbv = g_sb[jid];
    const float* __restrict__ sav = g_sa[jid];
    const int*   __restrict__ dst = args.dst[jid];
    float* __restrict__ m = g_m[jid];

    __shared__ float sw[8][32];
    __shared__ int   soff[8][32];

    const int wid  = threadIdx.x >> 5;
    const int lane = threadIdx.x & 31;
    const int node = blockIdx.x * 8 + wid;
    if (node >= NNODE) return;

    const int d = dst[node * DEG + lane];
    float x = sav[node] + sbv[d];
    float e = (x > 0.0f) ? x : 0.1f * expm1f(x);
    float w = expf(e);

    float wsum = w;
#pragma unroll
    for (int o = 16; o; o >>= 1) wsum += __shfl_xor_sync(0xffffffffu, wsum, o);

    sw[wid][lane]   = w;
    soff[wid][lane] = d * NBSTRIDE;
    __syncwarp();

    if (lane < 18) {
        float ax = 0.0f, ay = 0.0f;
        const float* bp = nb + 2 * lane;
#pragma unroll
        for (int j = 0; j < 32; j++) {
            float wj  = sw[wid][j];
            int   off = soff[wid][j];
            float2 v = *reinterpret_cast<const float2*>(bp + off);
            ax = fmaf(wj, v.x, ax);
            ay = fmaf(wj, v.y, ay);
        }
        float inv = 1.0f / wsum;
        int c = 2 * lane;
        float* mr = m + node * EMB;
        mr[c] = ax * inv;
        if (c + 1 < EMB) mr[c + 1] = ay * inv;
    }
}

// =====================================================================
// Kernel 3 (merged a+b): out = prelu([feat, m_pos, m_neg] @ W1 + b1) @ W2 + b2
// 4 threads per node (channel split of h), butterfly reduction for GEMM2.
// 256 threads = 64 nodes per block.
// =====================================================================
__global__ __launch_bounds__(256, 4) void update_kernel(
    const float* __restrict__ fa, const float* __restrict__ fb,
    const float* __restrict__ W1, const float* __restrict__ b1,
    const float* __restrict__ alpha_p,
    const float* __restrict__ W2, const float* __restrict__ b2,
    float* __restrict__ out)
{
    __shared__ __align__(16) float W1sh[105 * 72];  // rows padded 70 -> 72
    __shared__ __align__(16) float W2sh[72 * 36];   // 70 rows + 2 zero pad rows, cols 35 -> 36
    __shared__ __align__(16) ull b1p[36];
    __shared__ __align__(16) ull b2p[18];

    const int tid = threadIdx.x;
    for (int i = tid; i < 105 * 72; i += blockDim.x) {
        int k = i / 72, c = i % 72;
        W1sh[i] = (c < 70) ? W1[k * 70 + c] : 0.0f;
    }
    for (int i = tid; i < 72 * 36; i += blockDim.x) {
        int k = i / 36, c = i % 36;
        W2sh[i] = (k < 70 && c < EMB) ? W2[k * EMB + c] : 0.0f;
    }
    if (tid < 36) {
        int c = 2 * tid;
        b1p[tid] = pack2(b1[c], (c + 1 < 70) ? b1[c + 1] : 0.0f);
    }
    if (tid < 18) {
        int c = 2 * tid;
        b2p[tid] = pack2(b2[c], (c + 1 < EMB) ? b2[c + 1] : 0.0f);
    }
    __syncthreads();

    const int node_l = tid >> 2;
    const int role   = tid & 3;
    const int node   = blockIdx.x * 64 + node_l;            // 0 .. 2*NNODE-1
    const int nc     = (node < 2 * NNODE) ? node : (2 * NNODE - 1);

    const float* xr;
    const float* m0;
    const float* m1;
    if (nc < NNODE) {
        xr = fa + nc * EMB;
        m0 = g_m[0] + nc * EMB;
        m1 = g_m[1] + nc * EMB;
    } else {
        int nl = nc - NNODE;
        xr = fb + nl * EMB;
        m0 = g_m[2] + nl * EMB;
        m1 = g_m[3] + nl * EMB;
    }
    const float alpha = __ldg(alpha_p);

    // ---- GEMM1: this role computes h pairs [9*role, 9*role+9) ----
    ull acc[9];
#pragma unroll
    for (int i = 0; i < 9; i++) acc[i] = b1p[9 * role + i];

    const float* srcs[3] = { xr, m0, m1 };
    const ull* w1base = reinterpret_cast<const ull*>(W1sh) + 9 * role;
#pragma unroll 1
    for (int part = 0; part < 3; part++) {
        const float* x = srcs[part];
        const ull* wb = w1base + (part * EMB) * 36;
#pragma unroll 5
        for (int k = 0; k < EMB; k++) {
            float xv = __ldg(x + k);
            ull xx = pack2(xv, xv);
            const ull* wr = wb + k * 36;
#pragma unroll
            for (int i = 0; i < 9; i++) FMA2(acc[i], wr[i], xx, acc[i]);
        }
    }

    // ---- GEMM2: partials over this role's 18 k-values, all 36 out channels ----
    ull acc2[18];
#pragma unroll
    for (int i = 0; i < 18; i++) acc2[i] = (role == 0) ? b2p[i] : 0ull;

    const ull* w2 = reinterpret_cast<const ull*>(W2sh);
#pragma unroll
    for (int i = 0; i < 9; i++) {
        float h0, h1;
        unpack2(acc[i], h0, h1);
        h0 = (h0 > 0.0f) ? h0 : alpha * h0;   // PReLU
        h1 = (h1 > 0.0f) ? h1 : alpha * h1;
        int k0 = 18 * role + 2 * i;
        const ull* r0 = w2 + k0 * 18;
        const ull* r1 = r0 + 18;
        ull xx0 = pack2(h0, h0);
        ull xx1 = pack2(h1, h1);
#pragma unroll
        for (int j = 0; j < 18; j++) FMA2(acc2[j], r0[j], xx0, acc2[j]);
#pragma unroll
        for (int j = 0; j < 18; j++) FMA2(acc2[j], r1[j], xx1, acc2[j]);
    }

    // ---- butterfly reduction within the quad (lanes role^1, role^2) ----
#pragma unroll
    for (int o = 1; o <= 2; o <<= 1) {
#pragma unroll
        for (int j = 0; j < 18; j++) {
            ull other = __shfl_xor_sync(0xffffffffu, acc2[j], o);
            ADD2(acc2[j], acc2[j], other);
        }
    }

    // ---- writes: roles split the 18 output pairs (5,5,5,3) ----
    if (node < 2 * NNODE) {
        float* orow = out + node * EMB;
        int p0 = role * 5;
        int p1 = (role == 3) ? 18 : p0 + 5;
        for (int p = p0; p < p1; p++) {
            float v0, v1;
            unpack2(acc2[p], v0, v1);
            int c = 2 * p;
            orow[c] = v0;
            if (c + 1 < EMB) orow[c + 1] = v1;
        }
    }
}

// =====================================================================
// launch
// =====================================================================
extern "C" void kernel_launch(void* const* d_in, const int* in_sizes, int n_in,
                              void* d_out, int out_size) {
    const float* fa = (const float*)d_in[0];
    const float* fb = (const float*)d_in[1];

    TArgs t;
    const float* fsrc[4] = { fb, fb, fa, fa };
    const float* fdst[4] = { fa, fa, fb, fb };
    for (int j = 0; j < 4; j++) {
        t.fsrc[j] = fsrc[j];
        t.fdst[j] = fdst[j];
        t.W[j]   = (const float*)d_in[6 + 3 * j];
        t.b[j]   = (const float*)d_in[7 + 3 * j];
        t.att[j] = (const float*)d_in[8 + 3 * j];
    }
    AArgs a;
    a.dst[0] = (const int*)d_in[2];
    a.dst[1] = (const int*)d_in[3];
    a.dst[2] = (const int*)d_in[4];
    a.dst[3] = (const int*)d_in[5];

    const float* W1 = (const float*)d_in[18];
    const float* b1 = (const float*)d_in[19];
    const float* al = (const float*)d_in[20];
    const float* W2 = (const float*)d_in[21];
    const float* b2 = (const float*)d_in[22];
    float* out = (float*)d_out;

    dim3 tg((NNODE + 127) / 128, 4);
    transform_kernel<<<tg, 128>>>(t);

    dim3 ag((NNODE + 7) / 8, 4);
    agg_kernel<<<ag, 256>>>(a);

    dim3 ug((2 * NNODE + 63) / 64);
    update_kernel<<<ug, 256>>>(fa, fb, W1, b1, al, W2, b2, out);
}